// round 7
// baseline (speedup 1.0000x reference)
#include <cuda_runtime.h>
#include <math.h>
#include <stdint.h>

// YOLOv4 stride-8 head: [B, A*attrs, G, G] -> [B, G*G*A, attrs]
// B=16, A=3, attrs=85, G=76.
//
// Round-7: persistent grid-stride blocks, double-buffered smem tiles
// (HW_TILE=16, 2 x 16320B), bulk-TMA store of tile i overlapped with
// load/transform of tile i+1. Sigmoid via HW tanh.approx (1 MUFU vs 2).

#define N_ANCH   3
#define N_ATTRS  85
#define N_ROWS   255            // A * attrs
#define SCALE_XY 1.2f
#define HW_TILE  16
#define Q_PER_ROW (HW_TILE / 4) // 4 float4 per row
#define NTHREADS 256
#define TILE_ELEMS (HW_TILE * N_ROWS)      // 4080 floats = 16320 B
#define TOTAL_Q  (N_ROWS * Q_PER_ROW)      // 1020

__device__ __forceinline__ uint32_t smem_u32(const void* p) {
    uint32_t a;
    asm("{ .reg .u64 t; cvta.to.shared.u64 t, %1; cvt.u32.u64 %0, t; }"
        : "=r"(a) : "l"(p));
    return a;
}

__device__ __forceinline__ float fast_sigmoid(float v) {
    // sigmoid(x) = 0.5*tanh(x/2) + 0.5  -> single MUFU (tanh.approx)
    float t;
    asm("tanh.approx.f32 %0, %1;" : "=f"(t) : "f"(v * 0.5f));
    return fmaf(t, 0.5f, 0.5f);
}

__device__ __forceinline__ void transform4(float4 v, int row, int col0, int hw0,
                                           int G, float stride_f, float half_off,
                                           float* __restrict__ buf)
{
    int a = (row >= 2 * N_ATTRS) ? 2 : (row >= N_ATTRS) ? 1 : 0;
    int c = row - a * N_ATTRS;

    float4 r;
    if (c >= 4) {
        r.x = fast_sigmoid(v.x);
        r.y = fast_sigmoid(v.y);
        r.z = fast_sigmoid(v.z);
        r.w = fast_sigmoid(v.w);
    } else if (c < 2) {
        int hw = hw0 + col0;
        float g0, g1, g2, g3;
        if (c == 0) {
            g0 = (float)((hw + 0) % G); g1 = (float)((hw + 1) % G);
            g2 = (float)((hw + 2) % G); g3 = (float)((hw + 3) % G);
        } else {
            g0 = (float)((hw + 0) / G); g1 = (float)((hw + 1) / G);
            g2 = (float)((hw + 2) / G); g3 = (float)((hw + 3) / G);
        }
        float s0 = fast_sigmoid(v.x);
        float s1 = fast_sigmoid(v.y);
        float s2 = fast_sigmoid(v.z);
        float s3 = fast_sigmoid(v.w);
        r.x = fmaf(s0, SCALE_XY, g0 - half_off) * stride_f;
        r.y = fmaf(s1, SCALE_XY, g1 - half_off) * stride_f;
        r.z = fmaf(s2, SCALE_XY, g2 - half_off) * stride_f;
        r.w = fmaf(s3, SCALE_XY, g3 - half_off) * stride_f;
    } else {
        float aw = (a == 0) ? 12.f : (a == 1) ? 19.f : 40.f;
        float ah = (a == 0) ? 16.f : (a == 1) ? 36.f : 28.f;
        float m = (c == 2) ? aw : ah;
        r.x = __expf(v.x) * m;
        r.y = __expf(v.y) * m;
        r.z = __expf(v.z) * m;
        r.w = __expf(v.w) * m;
    }

    float* __restrict__ dst = buf + (size_t)(col0 * N_ANCH + a) * N_ATTRS + c;
    dst[0]          = r.x;
    dst[N_ROWS]     = r.y;
    dst[2 * N_ROWS] = r.z;
    dst[3 * N_ROWS] = r.w;
}

__global__ __launch_bounds__(NTHREADS)
void yolo_kernel(const float* __restrict__ x,
                 const int*   __restrict__ dim_raw,
                 float*       __restrict__ out,
                 int G, int GG, int tiles_per_b, int n_tiles_total)
{
    __shared__ __align__(16) float buf[2][TILE_ELEMS];   // 2 x 16320 B

    const int tid = threadIdx.x;

    int raw = *dim_raw;
    float dimv = (raw > 0 && raw < (1 << 20)) ? (float)raw : __int_as_float(raw);
    const float stride_f = __fdividef(dimv, (float)G);      // 8.0
    const float half_off = (SCALE_XY - 1.0f) * 0.5f;

    int p = 0;
    for (int tile = blockIdx.x; tile < n_tiles_total; tile += gridDim.x) {
        const int b   = tile / tiles_per_b;
        const int t   = tile - b * tiles_per_b;
        const int hw0 = t * HW_TILE;
        int cnt = GG - hw0; if (cnt > HW_TILE) cnt = HW_TILE;

        // make sure buf[p] is no longer being read by an in-flight bulk store
        if (tid == 0)
            asm volatile("cp.async.bulk.wait_group.read 1;" ::: "memory");
        __syncthreads();

        const float* __restrict__ inb = x + (size_t)b * N_ROWS * GG + hw0;
        float* __restrict__ bp = buf[p];

        if (cnt == HW_TILE) {
            #pragma unroll
            for (int k = 0; k < 4; ++k) {
                int i = tid + k * NTHREADS;
                if (i < TOTAL_Q) {
                    int row  = i >> 2;
                    int col0 = (i & 3) << 2;
                    float4 v = *(const float4*)(inb + (size_t)row * GG + col0);
                    transform4(v, row, col0, hw0, G, stride_f, half_off, bp);
                }
            }
        } else {
            #pragma unroll 2
            for (int i = tid; i < TOTAL_Q; i += NTHREADS) {
                int row  = i >> 2;
                int col0 = (i & 3) << 2;
                if (col0 < cnt) {
                    float4 v = *(const float4*)(inb + (size_t)row * GG + col0);
                    transform4(v, row, col0, hw0, G, stride_f, half_off, bp);
                }
            }
        }
        __syncthreads();

        if (tid == 0) {
            asm volatile("fence.proxy.async.shared::cta;" ::: "memory");
            float* gdst = out + ((size_t)b * GG + hw0) * N_ROWS;
            uint32_t sa = smem_u32(bp);
            uint32_t bytes = (uint32_t)(cnt * N_ROWS * sizeof(float));  // mult of 16
            asm volatile(
                "cp.async.bulk.global.shared::cta.bulk_group [%0], [%1], %2;"
                :: "l"(gdst), "r"(sa), "r"(bytes) : "memory");
            asm volatile("cp.async.bulk.commit_group;" ::: "memory");
        }
        p ^= 1;
    }

    // drain all outstanding bulk stores before CTA exit
    if (tid == 0)
        asm volatile("cp.async.bulk.wait_group 0;" ::: "memory");
}

extern "C" void kernel_launch(void* const* d_in, const int* in_sizes, int n_in,
                              void* d_out, int out_size)
{
    const float* x       = (const float*)d_in[0];
    const int*   dim_raw = (const int*)d_in[1];
    float*       out     = (float*)d_out;

    int n  = in_sizes[0];                        // B * 255 * G*G
    int B  = 16;
    int GG = n / (N_ROWS * B);                   // 5776
    int G  = (int)(sqrtf((float)GG) + 0.5f);     // 76

    int tiles_per_b   = (GG + HW_TILE - 1) / HW_TILE;   // 361
    int n_tiles_total = B * tiles_per_b;                // 5776

    int blocks = 148 * 6;                        // persistent: ~6 blocks/SM resident
    if (blocks > n_tiles_total) blocks = n_tiles_total;
    yolo_kernel<<<blocks, NTHREADS>>>(x, dim_raw, out, G, GG,
                                      tiles_per_b, n_tiles_total);
}